// round 16
// baseline (speedup 1.0000x reference)
#include <cuda_runtime.h>
#include <math.h>
#include <stdint.h>

#define DIM    768
#define HEADS  12
#define HD     64
#define HIDDEN 1536
#define BATCH  8
#define SEQ    1024
#define MROWS  (BATCH*SEQ)   // 8192

#if defined(__CUDA_ARCH_FEAT_SM103_ALL) || defined(__CUDA_ARCH_SPECIFIC__) || defined(__CUDA_ARCH_FAMILY_SPECIFIC__)
#define TC_OK 1
#else
#define TC_OK 0
#endif

// ---------------- scratch -----------------------------------------------------
__device__ float g_h   [MROWS * DIM];
__device__ float g_q   [BATCH*HEADS*SEQ*HD];    // pre-scaled by 0.125
__device__ float g_k   [BATCH*HEADS*SEQ*HD];
__device__ float g_v   [BATCH*HEADS*SEQ*HD];    // stored TRANSPOSED: [bh, d, kv]
__device__ float g_attn[MROWS * DIM];
__device__ float g_x1  [MROWS * DIM];
__device__ float g_hid [MROWS * HIDDEN];
__device__ float g_wT  [2304 * 768];

// ---------------- PTX helpers -------------------------------------------------
__device__ __forceinline__ uint32_t smem_u32(const void* p) {
    uint32_t a;
    asm("{ .reg .u64 t; cvta.to.shared.u64 t, %1; cvt.u32.u64 %0, t; }" : "=r"(a) : "l"(p));
    return a;
}
__device__ __forceinline__ uint32_t elect_one() {
    uint32_t p;
    asm volatile("{\n\t.reg .pred p;\n\telect.sync _|p, 0xFFFFFFFF;\n\tselp.b32 %0, 1, 0, p;\n\t}" : "=r"(p));
    return p;
}
#define MBAR_INIT(a, c) \
    asm volatile("mbarrier.init.shared.b64 [%0], %1;" :: "r"(a), "r"(c) : "memory")
#define MBAR_WAIT(a, ph) do { \
    uint32_t _m = (a), _p = (ph), _d; \
    asm volatile("{\n\t.reg .pred p;\n\tmbarrier.try_wait.parity.acquire.cta.shared::cta.b64 p, [%1], %2;\n\tselp.b32 %0, 1, 0, p;\n\t}" \
        : "=r"(_d) : "r"(_m), "r"(_p) : "memory"); \
    if (!_d) { \
        asm volatile("{\n\t.reg .pred P1;\n\tWL_%=:\n\tmbarrier.try_wait.parity.acquire.cta.shared::cta.b64 P1, [%0], %1, 0x989680;\n\t@P1 bra.uni WD_%=;\n\tbra.uni WL_%=;\n\tWD_%=:\n\t}" \
            :: "r"(_m), "r"(_p) : "memory"); \
    } \
} while (0)
#define MBAR_ARRIVE_RANK0(a) \
    asm volatile("{\n\t.reg .b32 ra;\n\tmapa.shared::cluster.u32 ra, %0, %1;\n\tmbarrier.arrive.shared::cluster.b64 _, [ra];\n\t}" \
        :: "r"(a), "r"(0) : "memory")
#define TC_ALLOC(sm_addr, n) \
    asm volatile("tcgen05.alloc.cta_group::1.sync.aligned.shared::cta.b32 [%0], %1;" :: "r"(sm_addr), "r"((uint32_t)(n)) : "memory")
#define TC_DEALLOC(t, n) \
    asm volatile("tcgen05.dealloc.cta_group::1.sync.aligned.b32 %0, %1;" :: "r"(t), "r"((uint32_t)(n)))
#define TC_RELINQ() \
    asm volatile("tcgen05.relinquish_alloc_permit.cta_group::1.sync.aligned;")
#define TC_ALLOC2(sm_addr, n) \
    asm volatile("tcgen05.alloc.cta_group::2.sync.aligned.shared::cta.b32 [%0], %1;" :: "r"(sm_addr), "r"((uint32_t)(n)) : "memory")
#define TC_DEALLOC2(t, n) \
    asm volatile("tcgen05.dealloc.cta_group::2.sync.aligned.b32 %0, %1;" :: "r"(t), "r"((uint32_t)(n)))
#define TC_RELINQ2() \
    asm volatile("tcgen05.relinquish_alloc_permit.cta_group::2.sync.aligned;")
#define TC_COMMIT(mb) \
    asm volatile("tcgen05.commit.cta_group::1.mbarrier::arrive::one.shared::cluster.b64 [%0];" :: "r"(mb) : "memory")
#define TC_COMMIT_MC2(mb) \
    asm volatile("tcgen05.commit.cta_group::2.mbarrier::arrive::one.shared::cluster.multicast::cluster.b64 [%0], %1;" \
        :: "r"(mb), "h"((uint16_t)0x3) : "memory")
#define TC_FENCE_AFTER()  asm volatile("tcgen05.fence::after_thread_sync;" ::: "memory")
#define TC_FENCE_BEFORE() asm volatile("tcgen05.fence::before_thread_sync;" ::: "memory")
#define TC_WAIT_LD()      asm volatile("tcgen05.wait::ld.sync.aligned;" ::: "memory")
#define TC_WAIT_ST()      asm volatile("tcgen05.wait::st.sync.aligned;" ::: "memory")
#define FENCE_ASYNC()     asm volatile("fence.proxy.async.shared::cta;" ::: "memory")
#define CLUSTER_SYNC() do { \
    asm volatile("barrier.cluster.arrive.aligned;" ::: "memory"); \
    asm volatile("barrier.cluster.wait.aligned;" ::: "memory"); } while (0)
#define CP_ASYNC16(dst, src) \
    asm volatile("cp.async.cg.shared.global [%0], [%1], 16;" :: "r"(dst), "l"(src) : "memory")
#define CP_COMMIT() asm volatile("cp.async.commit_group;" ::: "memory")
#define CP_WAIT0()  asm volatile("cp.async.wait_group 0;" ::: "memory")
#define CP_WAIT1()  asm volatile("cp.async.wait_group 1;" ::: "memory")
#define BAR_SYNC_N(id)   asm volatile("bar.sync %0, %1;" :: "r"(id), "r"(128) : "memory")
#define BAR_ARRIVE_N(id) asm volatile("bar.arrive %0, %1;" :: "r"(id), "r"(128) : "memory")
#define TC_LD_X32(r, t) \
    asm volatile("tcgen05.ld.sync.aligned.32x32b.x32.b32 " \
        "{%0,%1,%2,%3,%4,%5,%6,%7,%8,%9,%10,%11,%12,%13,%14,%15," \
        "%16,%17,%18,%19,%20,%21,%22,%23,%24,%25,%26,%27,%28,%29,%30,%31}, [%32];" \
        : "=r"((r)[0]),"=r"((r)[1]),"=r"((r)[2]),"=r"((r)[3]),"=r"((r)[4]),"=r"((r)[5]),"=r"((r)[6]),"=r"((r)[7]), \
          "=r"((r)[8]),"=r"((r)[9]),"=r"((r)[10]),"=r"((r)[11]),"=r"((r)[12]),"=r"((r)[13]),"=r"((r)[14]),"=r"((r)[15]), \
          "=r"((r)[16]),"=r"((r)[17]),"=r"((r)[18]),"=r"((r)[19]),"=r"((r)[20]),"=r"((r)[21]),"=r"((r)[22]),"=r"((r)[23]), \
          "=r"((r)[24]),"=r"((r)[25]),"=r"((r)[26]),"=r"((r)[27]),"=r"((r)[28]),"=r"((r)[29]),"=r"((r)[30]),"=r"((r)[31]) \
        : "r"(t))
#define TC_ST_X32(t, r) \
    asm volatile("tcgen05.st.sync.aligned.32x32b.x32.b32 [%0], " \
        "{%1,%2,%3,%4,%5,%6,%7,%8,%9,%10,%11,%12,%13,%14,%15,%16," \
        "%17,%18,%19,%20,%21,%22,%23,%24,%25,%26,%27,%28,%29,%30,%31,%32};" \
        :: "r"(t), \
           "r"((r)[0]),"r"((r)[1]),"r"((r)[2]),"r"((r)[3]),"r"((r)[4]),"r"((r)[5]),"r"((r)[6]),"r"((r)[7]), \
           "r"((r)[8]),"r"((r)[9]),"r"((r)[10]),"r"((r)[11]),"r"((r)[12]),"r"((r)[13]),"r"((r)[14]),"r"((r)[15]), \
           "r"((r)[16]),"r"((r)[17]),"r"((r)[18]),"r"((r)[19]),"r"((r)[20]),"r"((r)[21]),"r"((r)[22]),"r"((r)[23]), \
           "r"((r)[24]),"r"((r)[25]),"r"((r)[26]),"r"((r)[27]),"r"((r)[28]),"r"((r)[29]),"r"((r)[30]),"r"((r)[31]) \
        : "memory")

#if TC_OK
// SW128 K-major smem descriptor: LBO=1 (16B), SBO=64 (1024B), version=1, SW128
__device__ __forceinline__ uint64_t make_desc(uint32_t addr) {
    const uint64_t base = (uint64_t(2) << 61) | (uint64_t(1) << 46)
                        | (uint64_t(64) << 32) | (uint64_t(1) << 16);
    return base | ((uint64_t)(addr >> 4) & 0x3FFF);
}
__device__ __forceinline__ void mma_tf32(uint32_t d, uint64_t ad, uint64_t bd,
                                         uint32_t idesc, bool acc) {
    uint32_t en = acc ? 1u : 0u;
    asm volatile(
        "{\n\t.reg .pred p;\n\tsetp.ne.u32 p, %5, 0;\n\t"
        "tcgen05.mma.cta_group::1.kind::tf32 [%0], %1, %2, %3, {%4,%4,%4,%4}, p;\n\t}"
        :: "r"(d), "l"(ad), "l"(bd), "r"(idesc), "r"(0u), "r"(en) : "memory");
}
__device__ __forceinline__ void mma_tf32_ts(uint32_t d, uint32_t a, uint64_t bd,
                                            uint32_t idesc, bool acc) {
    uint32_t en = acc ? 1u : 0u;
    asm volatile(
        "{\n\t.reg .pred p;\n\tsetp.ne.u32 p, %5, 0;\n\t"
        "tcgen05.mma.cta_group::1.kind::tf32 [%0], [%1], %2, %3, {%4,%4,%4,%4}, p;\n\t}"
        :: "r"(d), "r"(a), "l"(bd), "r"(idesc), "r"(0u), "r"(en) : "memory");
}
__device__ __forceinline__ void mma_tf32_cg2(uint32_t d, uint64_t ad, uint64_t bd,
                                             uint32_t idesc, bool acc) {
    uint32_t en = acc ? 1u : 0u;
    asm volatile(
        "{\n\t.reg .pred p;\n\tsetp.ne.u32 p, %5, 0;\n\t"
        "tcgen05.mma.cta_group::2.kind::tf32 [%0], %1, %2, %3, {%4,%4,%4,%4,%4,%4,%4,%4}, p;\n\t}"
        :: "r"(d), "l"(ad), "l"(bd), "r"(idesc), "r"(0u), "r"(en) : "memory");
}
#endif

// ---------------- LayerNorm ---------------------------------------------------
__global__ __launch_bounds__(256)
void ln_kernel(const float* __restrict__ x, const float* __restrict__ g,
               const float* __restrict__ b, float* __restrict__ out)
{
    int row = blockIdx.x;
    int tid = threadIdx.x;
    const float* xr = x + (size_t)row * DIM;

    float v0 = xr[tid], v1 = xr[tid + 256], v2 = xr[tid + 512];
    float s  = v0 + v1 + v2;
    float ss = fmaf(v0, v0, fmaf(v1, v1, v2 * v2));

    #pragma unroll
    for (int o = 16; o > 0; o >>= 1) {
        s  += __shfl_xor_sync(0xffffffffu, s,  o);
        ss += __shfl_xor_sync(0xffffffffu, ss, o);
    }
    __shared__ float rs[8], rss[8];
    int w = tid >> 5, l = tid & 31;
    if (l == 0) { rs[w] = s; rss[w] = ss; }
    __syncthreads();
    float ts = 0.f, tss = 0.f;
    #pragma unroll
    for (int i = 0; i < 8; i++) { ts += rs[i]; tss += rss[i]; }

    const float inv_n = 1.0f / (float)DIM;
    float mu   = ts * inv_n;
    float var  = tss * inv_n - mu * mu;
    float rstd = rsqrtf(var + 1e-5f);

    float* orow = out + (size_t)row * DIM;
    orow[tid      ] = (v0 - mu) * rstd * g[tid      ] + b[tid      ];
    orow[tid + 256] = (v1 - mu) * rstd * g[tid + 256] + b[tid + 256];
    orow[tid + 512] = (v2 - mu) * rstd * g[tid + 512] + b[tid + 512];
}

// ---------------- weight transpose: Wt[N,K] = W[K,N] --------------------------
__global__ __launch_bounds__(256)
void transpose_kernel(const float* __restrict__ W, float* __restrict__ Wt,
                      int K, int N)
{
    __shared__ float t[32][33];
    int tx = threadIdx.x & 31, ty = threadIdx.x >> 5;
    int bx = blockIdx.x, by = blockIdx.y;
    #pragma unroll
    for (int i = 0; i < 4; i++)
        t[ty + i * 8][tx] = W[(size_t)(by * 32 + ty + i * 8) * N + bx * 32 + tx];
    __syncthreads();
    #pragma unroll
    for (int i = 0; i < 4; i++)
        Wt[(size_t)(bx * 32 + ty + i * 8) * K + by * 32 + tx] = t[tx][ty + i * 8];
}

// ---------------- 2CTA tcgen05 tf32 GEMM: 256x256 cluster tile ----------------
// Cluster (2,1,1): rank = M-half. Each CTA loads its 128 A-rows and its 128
// B-N-rows per chunk (same smem offsets). Leader (rank 0) issues M=256 N=256
// cg2 MMAs; commit multicasts to both CTAs' FREE mbar. D: per-CTA 128x256.
#define EPI_QKV      0
#define EPI_BIASRES  1
#define EPI_BIASGELU 2

#define STG_BYTES 32768                   // A 16KB + B 16KB per CTA
#define TG_SMEM   (1024 + 2*STG_BYTES)    // 66560 -> 2 CTAs/SM

template<int EPI>
__global__ __launch_bounds__(256, 2) __cluster_dims__(2, 1, 1)
void tgemm_kernel(const float* __restrict__ A, const float* __restrict__ Bt,
                  int M, int N, int K,
                  const float* __restrict__ bias, const float* __restrict__ res,
                  float* __restrict__ C,
                  float* __restrict__ Cq, float* __restrict__ Ck, float* __restrict__ Cv)
{
#if TC_OK
    extern __shared__ char sm[];
    const uint32_t smb = smem_u32(sm);
    const int tid = threadIdx.x;
    const int wid = tid >> 5;
    const int lid = tid & 31;
    uint32_t rank;
    asm("mov.u32 %0, %%cluster_ctarank;" : "=r"(rank));
    const int m0 = blockIdx.y * 256;
    const int n0 = (blockIdx.x >> 1) * 256;
    const int nk = K / 32;

    const uint32_t OFF_TM = 0;
    const uint32_t RDY = 8, FRE = 24;     // RDY: 8/16 (count 2), FRE: 24/32 (count 1)
    const uint32_t OFF_S = 1024;

    if (wid == 0) { TC_ALLOC2(smb + OFF_TM, 256); TC_RELINQ2(); }
    if (tid == 0) {
        MBAR_INIT(smb + RDY, 2); MBAR_INIT(smb + RDY + 8, 2);
        MBAR_INIT(smb + FRE, 1); MBAR_INIT(smb + FRE + 8, 1);
    }
    __syncthreads();
    uint32_t tmem;
    asm volatile("ld.shared.b32 %0, [%1];" : "=r"(tmem) : "r"(smb + OFF_TM));
    TC_FENCE_AFTER();
    CLUSTER_SYNC();   // mbarriers + alloc visible cluster-wide before any cross-CTA op

    // idesc: c=F32, a=b=TF32, M=256, N=256
    const uint32_t idesc = (1u << 4) | (2u << 7) | (2u << 10)
                         | (32u << 17) | (16u << 24);

    // per chunk: this CTA's A half (128 rows) + B half (128 N-rows), 16KB each
    auto load_chunk = [&](int c, int st) {
        const int k0 = c * 32;
        const uint32_t base = smb + OFF_S + st * STG_BYTES;
        #pragma unroll
        for (int t = 0; t < 4; t++) {
            int id  = tid + t * 256;
            int row = id >> 3;
            int kc4 = (id & 7) * 4;
            uint32_t byte = row * 128 + kc4 * 4;
            uint32_t sw   = byte ^ ((byte >> 3) & 0x70);
            CP_ASYNC16(base + sw,
                       A + (size_t)(m0 + rank * 128 + row) * K + k0 + kc4);
        }
        #pragma unroll
        for (int t = 0; t < 4; t++) {
            int id  = tid + t * 256;
            int row = id >> 3;
            int kc4 = (id & 7) * 4;
            uint32_t byte = row * 128 + kc4 * 4;
            uint32_t sw   = byte ^ ((byte >> 3) & 0x70);
            CP_ASYNC16(base + 16384 + sw,
                       Bt + (size_t)(n0 + rank * 128 + row) * K + k0 + kc4);
        }
        CP_COMMIT();
    };

    load_chunk(0, 0); load_chunk(1, 1);

    for (int c = 0; c < nk; c++) {
        const int st = c & 1;
        const int u  = c >> 1;
        CP_WAIT1();
        __syncthreads();
        FENCE_ASYNC();
        if (tid == 0) MBAR_ARRIVE_RANK0(smb + RDY + st * 8);
        if (rank == 0 && wid == 0) {
            const uint32_t base = smb + OFF_S + st * STG_BYTES;
            uint64_t ad = make_desc(base);
            uint64_t bd = make_desc(base + 16384);
            if (elect_one()) {
                MBAR_WAIT(smb + RDY + st * 8, u & 1);
                TC_FENCE_AFTER();
                #pragma unroll
                for (int ks = 0; ks < 4; ks++)
                    mma_tf32_cg2(tmem, ad + ks * 2, bd + ks * 2, idesc,
                                 (c > 0) || (ks > 0));
                TC_COMMIT_MC2(smb + FRE + st * 8);
            }
        }
        if (c + 2 < nk) {
            MBAR_WAIT(smb + FRE + st * 8, u & 1);   // MMA(c) done -> stage free (both CTAs)
            load_chunk(c + 2, st);
        } else {
            CP_COMMIT();
        }
    }
    MBAR_WAIT(smb + FRE + ((nk - 1) & 1) * 8, ((nk - 1) >> 1) & 1);
    TC_FENCE_AFTER();

    // epilogue: this CTA's 128 rows x 256 cols
    const int rw = wid & 3, ch = wid >> 2;
    const int r  = m0 + (int)rank * 128 + rw * 32 + lid;
    #pragma unroll
    for (int g = 0; g < 4; g++) {
        const int col0 = ch * 128 + g * 32;
        uint32_t d[32];
        TC_LD_X32(d, tmem + col0);
        TC_WAIT_LD();
        const int cbase = n0 + col0;
        if (EPI == EPI_QKV) {
            int which = cbase / DIM;
            int rem   = cbase - which * DIM;
            int h     = rem >> 6;
            int d0    = rem & 63;
            int bb    = r >> 10, n = r & 1023;
            if (which == 2) {
                float* dstv = Cv + ((size_t)(bb * HEADS + h) * HD + d0) * SEQ + n;
                #pragma unroll
                for (int j = 0; j < 32; j++)
                    dstv[(size_t)j * SEQ] = __uint_as_float(d[j]);
            } else {
                const float sc = (which == 0) ? 0.125f : 1.0f;
                float* p = (which == 0) ? Cq : Ck;
                float* dst = p + (((size_t)(bb * HEADS + h) * SEQ + n) * HD + d0);
                #pragma unroll
                for (int j4 = 0; j4 < 8; j4++)
                    *(float4*)(dst + j4 * 4) = make_float4(
                        __uint_as_float(d[j4*4+0]) * sc, __uint_as_float(d[j4*4+1]) * sc,
                        __uint_as_float(d[j4*4+2]) * sc, __uint_as_float(d[j4*4+3]) * sc);
            }
        } else if (EPI == EPI_BIASRES) {
            const float4* rp = (const float4*)(res  + (size_t)r * N + cbase);
            const float4* bp = (const float4*)(bias + cbase);
            float4*       cp = (float4*)(C + (size_t)r * N + cbase);
            #pragma unroll
            for (int j4 = 0; j4 < 8; j4++) {
                float4 rv = rp[j4], bv = bp[j4], o;
                o.x = rv.x + __uint_as_float(d[j4*4+0]) + bv.x;
                o.y = rv.y + __uint_as_float(d[j4*4+1]) + bv.y;
                o.z = rv.z + __uint_as_float(d[j4*4+2]) + bv.z;
                o.w = rv.w + __uint_as_float(d[j4*4+3]) + bv.w;
                cp[j4] = o;
            }
        } else {
            const float4* bp = (const float4*)(bias + cbase);
            float4*       cp = (float4*)(C + (size_t)r * N + cbase);
            #pragma unroll
            for (int j4 = 0; j4 < 8; j4++) {
                float4 bv = bp[j4], o;
                float t0 = __uint_as_float(d[j4*4+0]) + bv.x;
                float t1 = __uint_as_float(d[j4*4+1]) + bv.y;
                float t2 = __uint_as_float(d[j4*4+2]) + bv.z;
                float t3 = __uint_as_float(d[j4*4+3]) + bv.w;
                o.x = 0.5f * t0 * (1.0f + erff(t0 * 0.70710678118654752f));
                o.y = 0.5f * t1 * (1.0f + erff(t1 * 0.70710678118654752f));
                o.z = 0.5f * t2 * (1.0f + erff(t2 * 0.70710678118654752f));
                o.w = 0.5f * t3 * (1.0f + erff(t3 * 0.70710678118654752f));
                cp[j4] = o;
            }
        }
    }
    TC_FENCE_BEFORE();
    __syncthreads();
    CLUSTER_SYNC();
    if (wid == 0) {
        TC_DEALLOC2(tmem, 256);
    }
#endif
}

// ---------------- tcgen05 flash attention v9 (proven, unchanged) --------------
#define NT 16
#define AT_SMEM (1024 + 32768 + 2*16384 + 3*16384)   // 115712 -> 2 CTAs/SM

__global__ __launch_bounds__(256, 2)
void attn_tc_kernel(const float* __restrict__ Q, const float* __restrict__ K,
                    const float* __restrict__ Vt, const float* __restrict__ rpe,
                    float* __restrict__ out)
{
#if TC_OK
    extern __shared__ char sm[];
    const uint32_t smb = smem_u32(sm);
    const int tid = threadIdx.x;
    const int wid = tid >> 5;
    const int lid = tid & 31;
    const int g   = wid >> 2;
    const int lw  = wid & 3;
    const int rsub = lw * 32 + lid;
    const int gtid = tid & 127;

    const int b  = blockIdx.x;
    const int hq = blockIdx.y;
    const int h  = hq >> 3;
    const int qt = hq & 7;
    const int bh = b * HEADS + h;
    const int q0 = qt * 128;

    const uint32_t OFF_TM = 0;
    const uint32_t MB1 = 8, MB2 = 24, FIN = 40;
    const uint32_t OFF_Q = 1024;
    const uint32_t OFF_K = 1024 + 32768;
    const uint32_t OFF_V = 1024 + 32768 + 32768;

    if (wid == 0) { TC_ALLOC(smb + OFF_TM, 256); TC_RELINQ(); }
    if (tid == 0) {
        MBAR_INIT(smb + MB1, 1); MBAR_INIT(smb + MB1 + 8, 1);
        MBAR_INIT(smb + MB2, 1); MBAR_INIT(smb + MB2 + 8, 1);
        MBAR_INIT(smb + FIN, 1); MBAR_INIT(smb + FIN + 8, 1);
    }
    __syncthreads();
    uint32_t tmem;
    asm volatile("ld.shared.b32 %0, [%1];" : "=r"(tmem) : "r"(smb + OFF_TM));
    TC_FENCE_AFTER();
    const uint32_t tmem_S = tmem + g * 64;
    const uint32_t tmem_O = tmem + 128;

    if (g == 0) {
        uint32_t z[32];
        #pragma unroll
        for (int i = 0; i < 32; i++) z[i] = 0u;
        TC_ST_X32(tmem_O, z);
        TC_ST_X32(tmem_O + 32, z);
        TC_WAIT_ST();
        TC_FENCE_BEFORE();
    }

    const float* Qb  = Q  + ((size_t)bh * SEQ + q0) * HD;
    const float* Kb0 = K  + (size_t)bh * SEQ * HD;
    const float* Vb0 = Vt + (size_t)bh * HD * SEQ;

    auto load_K_all = [&](int t2, int kslot) {
        const int kv0 = t2 * 64;
        #pragma unroll
        for (int t = 0; t < 4; t++) {
            int id  = tid + t * 256;
            int row = id >> 4;
            int c4  = (id & 15) * 4;
            int chunk = c4 >> 5;
            uint32_t byte = row * 128 + (c4 & 31) * 4;
            uint32_t sw   = byte ^ ((byte >> 3) & 0x70);
            CP_ASYNC16(smb + OFF_K + kslot * 16384 + chunk * 8192 + sw,
                       Kb0 + (size_t)(kv0 + row) * HD + c4);
        }
    };
    auto load_V_all = [&](int t2) {
        const int kv0 = t2 * 64, vslot = t2 % 3;
        #pragma unroll
        for (int t = 0; t < 4; t++) {
            int id  = tid + t * 256;
            int row = id >> 4;
            int c4  = (id & 15) * 4;
            int chunk = c4 >> 5;
            uint32_t byte = row * 128 + (c4 & 31) * 4;
            uint32_t sw   = byte ^ ((byte >> 3) & 0x70);
            CP_ASYNC16(smb + OFF_V + vslot * 16384 + chunk * 8192 + sw,
                       Vb0 + (size_t)row * SEQ + kv0 + c4);
        }
    };
    auto load_K_grp = [&](int t2) {
        const int kv0 = t2 * 64;
        #pragma unroll
        for (int t = 0; t < 8; t++) {
            int id  = gtid + t * 128;
            int row = id >> 4;
            int c4  = (id & 15) * 4;
            int chunk = c4 >> 5;
            uint32_t byte = row * 128 + (c4 & 31) * 4;
            uint32_t sw   = byte ^ ((byte >> 3) & 0x70);
            CP_ASYNC16(smb + OFF_K + g * 16384 + chunk * 8192 + sw,
                       Kb0 + (size_t)(kv0 + row) * HD + c4);
        }
    };
    auto load_V_grp = [&](int t2) {
        const int kv0 = t2 * 64, vslot = t2 % 3;
        #pragma unroll
        for (int t = 0; t < 8; t++) {
            int id  = gtid + t * 128;
            int row = id >> 4;
            int c4  = (id & 15) * 4;
            int chunk = c4 >> 5;
            uint32_t byte = row * 128 + (c4 & 31) * 4;
            uint32_t sw   = byte ^ ((byte >> 3) & 0x70);
            CP_ASYNC16(smb + OFF_V + vslot * 16384 + chunk * 8192 + sw,
                       Vb0 + (size_t)row * SEQ + kv0 + c4);
        }
    };

    // prologue
    #pragma unroll
    for (int t = 0; t < 8; t++) {
        int id  = tid + t * 256;
        int row = id >> 4;
        int c4  = (id & 15) * 4;
        int chunk = c4 >> 5;
        uint32_t byte = row * 128 + (c4 & 31) * 4;
        uint32_t sw   = byte ^ ((byte >> 3) & 0x70);
        CP_ASYNC16(smb + OFF_Q + chunk * 16384 + sw, Qb + row * HD + c4);
    }
    load_K_all(0, 0); load_V_all(0);
    load_K_all(1, 1); load_V_all(1);
    CP_COMMIT();
    CP_WAIT0();
    __syncthreads();
    FENCE_ASYNC();

    const uint32_t idesc1 = (1u << 4) | (2u << 7) | (2u << 10)
                          | (8u << 17) | (8u << 24);

    float lsum = 0.f;

    for (int j = 0; j < 8; j++) {
        const int t = 2 * j + g;

        CP_WAIT0();
        BAR_SYNC_N(1 + g);
        FENCE_ASYNC();

        if (lw == 0) {
            TC_FENCE_AFTER();
            if (elect_one()) {
                #pragma unroll
                for (int c = 0; c < 2; c++) {
                    uint64_t ad = make_desc(smb + OFF_Q + c * 16384);
                    uint64_t bd = make_desc(smb + OFF_K + g * 16384 + c * 8192);
                    #pragma unroll
                    for (int ks = 0; ks < 4; ks++)
                        mma_tf32(tmem_S, ad + ks * 2, bd + ks * 2, idesc1,
                                 (c > 0) || (ks > 0));
                }
                TC_COMMIT(smb + MB1 + g * 8);
            }
        }

        const float4* bp = (const float4*)(rpe + ((size_t)h * SEQ + q0 + rsub) * SEQ
                                           + t * 64);
        float4 b0[8];
        #pragma unroll
        for (int i = 0; i < 8; i++) b0[i] = bp[i];

        if (j < 7) {
            const int gate = j + g - 1;
            if (gate >= 0) MBAR_WAIT(smb + MB2 + (1 - g) * 8, gate & 1);
            load_V_grp(t + 2);
            CP_COMMIT();
        }

        MBAR_WAIT(smb + MB1 + g * 8, j & 1);
        TC_FENCE_AFTER();

        if (j < 7) { load_K_grp(t + 2); CP_COMMIT(); }

        {
            uint32_t d[32];
            TC_LD_X32(d, tmem_S);
            TC_WAIT_LD();
            float4 b1[8];
            #pragma unroll
            for (int i = 0; i < 8; i++) b1[i] = bp[8 + i];
            #pragma unroll
            for (int j4 = 0; j4 < 8; j4++) {
                float4 bv = b0[j4];
                float p0 = __expf(__uint_as_float(d[j4*4+0]) + bv.x);
                float p1 = __expf(__uint_as_float(d[j4*4+1]) + bv.y);
                float p2 = __expf(__uint_as_float(d[j4*4+2]) + bv.z);
                float p3 = __expf(__uint_as_float(d[j4*4+3]) + bv.w);
                lsum += (p0 + p1) + (p2 + p3);
                d[j4*4+0] = __float_as_uint(p0);
                d[j4*4+1] = __float_as_uint(p1);
                d[j4*4+2] = __float_as_uint(p2);
                d[j4*4+3] = __float_as_uint(p3);
            }
            TC_ST_X32(tmem_S, d);
            TC_LD_X32(d, tmem_S + 32);
            TC_WAIT_LD();
            #pragma unroll
            for (int j4 = 0; j4 < 8; j4++) {
                float4 bv = b1[j4];
                float p0 = __expf(__uint_as_float(d[j4*4+0]) + bv.x);
                float p1 = __expf(__uint_as_float(d[j4*4+1]) + bv.y);
                float p2 = __expf(__uint_as_float(d[j4*4+2]) + bv.z);
                float p3 = __expf(__uint_as_float(d[j4*4+3]) + bv.w);
                lsum += (p0 + p1) + (p2 + p3);
                d[j4*4+0] = __float_as_uint(p0);
                d[j4*4+1] = __float_as_uint(p1);
                d[j4*4+2] = __float_as_uint(p2);
                d[j4*4+3] = __float_as_uint(p3);
            }
            TC_ST_X32(tmem_S + 32, d);
            TC_WAIT_ST();
            TC_FENCE_BEFORE();
        }

        if (lw == 0) {
            BAR_SYNC_N(3 + g);
            TC_FENCE_AFTER();
            if (elect_one()) {
                const int vs = t % 3;
                #pragma unroll
                for (int s = 0; s < 8; s++) {
                    uint64_t bd = make_desc(smb + OFF_V + vs * 16384 + (s >> 2) * 8192)
                                + (s & 3) * 2;
                    mma_tf32_ts(tmem_O, tmem_S + s * 8, bd, idesc1, true);
                }
                TC_COMMIT(smb + MB2 + g * 8);
                if (j == 7) TC_COMMIT(smb + FIN + g * 8);
            }
        } else {
            BAR_ARRIVE_N(3 + g);
        }
    }

    __syncthreads();
    MBAR_WAIT(smb + FIN, 0);
    MBAR_WAIT(smb + FIN + 8, 0);
    TC_FENCE_AFTER();

    float* lsh = (float*)(sm + OFF_V);
    lsh[g * 128 + rsub] = lsum;
    __syncthreads();
    const float inv = 1.0f / (lsh[rsub] + lsh[128 + rsub]);

    {
        uint32_t d[32];
        TC_LD_X32(d, tmem_O + g * 32);
        TC_WAIT_LD();
        float* ob = out + ((size_t)(b * SEQ + q0 + rsub)) * DIM + h * HD + g * 32;
        #pragma unroll
        for (int j4 = 0; j4 < 8; j4++)
            *(float4*)(ob + j4 * 4) = make_float4(
                __uint_as_float(d[j4*4+0]) * inv, __uint_as_float(d[j4*4+1]) * inv,
                __uint_as_float(d[j4*4+2]) * inv, __uint_as_float(d[j4*4+3]) * inv);
    }
    TC_FENCE_BEFORE();
    __syncthreads();
    if (wid == 0) {
        TC_DEALLOC(tmem, 256);
    }
#endif
}

// ---------------- launch ------------------------------------------------------
extern "C" void kernel_launch(void* const* d_in, const int* in_sizes, int n_in,
                              void* d_out, int out_size)
{
    const float* x      = (const float*)d_in[0];
    const float* rpe    = (const float*)d_in[1];
    const float* qkv_w  = (const float*)d_in[2];
    const float* proj_w = (const float*)d_in[3];
    const float* proj_b = (const float*)d_in[4];
    const float* ln1_g  = (const float*)d_in[5];
    const float* ln1_b  = (const float*)d_in[6];
    const float* ln2_g  = (const float*)d_in[7];
    const float* ln2_b  = (const float*)d_in[8];
    const float* fc1_w  = (const float*)d_in[9];
    const float* fc1_b  = (const float*)d_in[10];
    const float* fc2_w  = (const float*)d_in[11];
    const float* fc2_b  = (const float*)d_in[12];
    float* out = (float*)d_out;

    float *p_h, *p_q, *p_k, *p_v, *p_attn, *p_x1, *p_hid, *p_wT;
    cudaGetSymbolAddress((void**)&p_h,    g_h);
    cudaGetSymbolAddress((void**)&p_q,    g_q);
    cudaGetSymbolAddress((void**)&p_k,    g_k);
    cudaGetSymbolAddress((void**)&p_v,    g_v);
    cudaGetSymbolAddress((void**)&p_attn, g_attn);
    cudaGetSymbolAddress((void**)&p_x1,   g_x1);
    cudaGetSymbolAddress((void**)&p_hid,  g_hid);
    cudaGetSymbolAddress((void**)&p_wT,   g_wT);

    cudaFuncSetAttribute(attn_tc_kernel,
                         cudaFuncAttributeMaxDynamicSharedMemorySize, AT_SMEM);
    cudaFuncSetAttribute(tgemm_kernel<EPI_QKV>,
                         cudaFuncAttributeMaxDynamicSharedMemorySize, TG_SMEM);
    cudaFuncSetAttribute(tgemm_kernel<EPI_BIASRES>,
                         cudaFuncAttributeMaxDynamicSharedMemorySize, TG_SMEM);
    cudaFuncSetAttribute(tgemm_kernel<EPI_BIASGELU>,
                         cudaFuncAttributeMaxDynamicSharedMemorySize, TG_SMEM);

    // 1) LN1
    ln_kernel<<<MROWS, 256>>>(x, ln1_g, ln1_b, p_h);

    // 2) QKV GEMM: clusters of 2, 256x256 tile (x = 2*n_tiles, y = MROWS/256)
    transpose_kernel<<<dim3(3 * DIM / 32, DIM / 32), 256>>>(qkv_w, p_wT, DIM, 3 * DIM);
    tgemm_kernel<EPI_QKV><<<dim3(2 * (3 * DIM / 256), MROWS / 256), 256, TG_SMEM>>>(
        p_h, p_wT, MROWS, 3 * DIM, DIM,
        nullptr, nullptr, nullptr, p_q, p_k, p_v);

    // 3) two-warp-group tensor-core flash attention (v9)
    attn_tc_kernel<<<dim3(BATCH, HEADS * (SEQ / 128)), 256, AT_SMEM>>>(
        p_q, p_k, p_v, rpe, p_attn);

    // 4) proj + bias + residual
    transpose_kernel<<<dim3(DIM / 32, DIM / 32), 256>>>(proj_w, p_wT, DIM, DIM);
    tgemm_kernel<EPI_BIASRES><<<dim3(2 * (DIM / 256), MROWS / 256), 256, TG_SMEM>>>(
        p_attn, p_wT, MROWS, DIM, DIM,
        proj_b, x, p_x1, nullptr, nullptr, nullptr);

    // 5) LN2
    ln_kernel<<<MROWS, 256>>>(p_x1, ln2_g, ln2_b, p_h);

    // 6) FC1 + GELU
    transpose_kernel<<<dim3(HIDDEN / 32, DIM / 32), 256>>>(fc1_w, p_wT, DIM, HIDDEN);
    tgemm_kernel<EPI_BIASGELU><<<dim3(2 * (HIDDEN / 256), MROWS / 256), 256, TG_SMEM>>>(
        p_h, p_wT, MROWS, HIDDEN, DIM,
        fc1_b, nullptr, p_hid, nullptr, nullptr, nullptr);

    // 7) FC2 + bias + residual
    transpose_kernel<<<dim3(DIM / 32, HIDDEN / 32), 256>>>(fc2_w, p_wT, HIDDEN, DIM);
    tgemm_kernel<EPI_BIASRES><<<dim3(2 * (DIM / 256), MROWS / 256), 256, TG_SMEM>>>(
        p_hid, p_wT, MROWS, DIM, HIDDEN,
        fc2_b, p_x1, out, nullptr, nullptr, nullptr);
}

// round 17
// speedup vs baseline: 1.0237x; 1.0237x over previous
#include <cuda_runtime.h>
#include <math.h>
#include <stdint.h>

#define DIM    768
#define HEADS  12
#define HD     64
#define HIDDEN 1536
#define BATCH  8
#define SEQ    1024
#define MROWS  (BATCH*SEQ)   // 8192

#if defined(__CUDA_ARCH_FEAT_SM103_ALL) || defined(__CUDA_ARCH_SPECIFIC__) || defined(__CUDA_ARCH_FAMILY_SPECIFIC__)
#define TC_OK 1
#else
#define TC_OK 0
#endif

// ---------------- scratch -----------------------------------------------------
__device__ float g_h   [MROWS * DIM];
__device__ float g_q   [BATCH*HEADS*SEQ*HD];    // pre-scaled by 0.125
__device__ float g_k   [BATCH*HEADS*SEQ*HD];
__device__ float g_v   [BATCH*HEADS*SEQ*HD];    // stored TRANSPOSED: [bh, d, kv]
__device__ float g_attn[MROWS * DIM];
__device__ float g_x1  [MROWS * DIM];
__device__ float g_hid [MROWS * HIDDEN];
__device__ float g_wT_qkv [2304 * 768];
__device__ float g_wT_proj[768 * 768];
__device__ float g_wT_fc1 [1536 * 768];
__device__ float g_wT_fc2 [768 * 1536];

// ---------------- PTX helpers -------------------------------------------------
__device__ __forceinline__ uint32_t smem_u32(const void* p) {
    uint32_t a;
    asm("{ .reg .u64 t; cvta.to.shared.u64 t, %1; cvt.u32.u64 %0, t; }" : "=r"(a) : "l"(p));
    return a;
}
__device__ __forceinline__ uint32_t elect_one() {
    uint32_t p;
    asm volatile("{\n\t.reg .pred p;\n\telect.sync _|p, 0xFFFFFFFF;\n\tselp.b32 %0, 1, 0, p;\n\t}" : "=r"(p));
    return p;
}
#define MBAR_INIT(a, c) \
    asm volatile("mbarrier.init.shared.b64 [%0], %1;" :: "r"(a), "r"(c) : "memory")
#define MBAR_WAIT(a, ph) do { \
    uint32_t _m = (a), _p = (ph), _d; \
    asm volatile("{\n\t.reg .pred p;\n\tmbarrier.try_wait.parity.acquire.cta.shared::cta.b64 p, [%1], %2;\n\tselp.b32 %0, 1, 0, p;\n\t}" \
        : "=r"(_d) : "r"(_m), "r"(_p) : "memory"); \
    if (!_d) { \
        asm volatile("{\n\t.reg .pred P1;\n\tWL_%=:\n\tmbarrier.try_wait.parity.acquire.cta.shared::cta.b64 P1, [%0], %1, 0x989680;\n\t@P1 bra.uni WD_%=;\n\tbra.uni WL_%=;\n\tWD_%=:\n\t}" \
            :: "r"(_m), "r"(_p) : "memory"); \
    } \
} while (0)
#define TC_ALLOC(sm_addr, n) \
    asm volatile("tcgen05.alloc.cta_group::1.sync.aligned.shared::cta.b32 [%0], %1;" :: "r"(sm_addr), "r"((uint32_t)(n)) : "memory")
#define TC_DEALLOC(t, n) \
    asm volatile("tcgen05.dealloc.cta_group::1.sync.aligned.b32 %0, %1;" :: "r"(t), "r"((uint32_t)(n)))
#define TC_RELINQ() \
    asm volatile("tcgen05.relinquish_alloc_permit.cta_group::1.sync.aligned;")
#define TC_COMMIT(mb) \
    asm volatile("tcgen05.commit.cta_group::1.mbarrier::arrive::one.shared::cluster.b64 [%0];" :: "r"(mb) : "memory")
#define TC_FENCE_AFTER()  asm volatile("tcgen05.fence::after_thread_sync;" ::: "memory")
#define TC_FENCE_BEFORE() asm volatile("tcgen05.fence::before_thread_sync;" ::: "memory")
#define TC_WAIT_LD()      asm volatile("tcgen05.wait::ld.sync.aligned;" ::: "memory")
#define TC_WAIT_ST()      asm volatile("tcgen05.wait::st.sync.aligned;" ::: "memory")
#define FENCE_ASYNC()     asm volatile("fence.proxy.async.shared::cta;" ::: "memory")
#define CP_ASYNC16(dst, src) \
    asm volatile("cp.async.cg.shared.global [%0], [%1], 16;" :: "r"(dst), "l"(src) : "memory")
#define CP_COMMIT() asm volatile("cp.async.commit_group;" ::: "memory")
#define CP_WAIT0()  asm volatile("cp.async.wait_group 0;" ::: "memory")
#define CP_WAIT1()  asm volatile("cp.async.wait_group 1;" ::: "memory")
#define BAR_SYNC_N(id)   asm volatile("bar.sync %0, %1;" :: "r"(id), "r"(128) : "memory")
#define BAR_ARRIVE_N(id) asm volatile("bar.arrive %0, %1;" :: "r"(id), "r"(128) : "memory")
#define TC_LD_X32(r, t) \
    asm volatile("tcgen05.ld.sync.aligned.32x32b.x32.b32 " \
        "{%0,%1,%2,%3,%4,%5,%6,%7,%8,%9,%10,%11,%12,%13,%14,%15," \
        "%16,%17,%18,%19,%20,%21,%22,%23,%24,%25,%26,%27,%28,%29,%30,%31}, [%32];" \
        : "=r"((r)[0]),"=r"((r)[1]),"=r"((r)[2]),"=r"((r)[3]),"=r"((r)[4]),"=r"((r)[5]),"=r"((r)[6]),"=r"((r)[7]), \
          "=r"((r)[8]),"=r"((r)[9]),"=r"((r)[10]),"=r"((r)[11]),"=r"((r)[12]),"=r"((r)[13]),"=r"((r)[14]),"=r"((r)[15]), \
          "=r"((r)[16]),"=r"((r)[17]),"=r"((r)[18]),"=r"((r)[19]),"=r"((r)[20]),"=r"((r)[21]),"=r"((r)[22]),"=r"((r)[23]), \
          "=r"((r)[24]),"=r"((r)[25]),"=r"((r)[26]),"=r"((r)[27]),"=r"((r)[28]),"=r"((r)[29]),"=r"((r)[30]),"=r"((r)[31]) \
        : "r"(t))
#define TC_ST_X32(t, r) \
    asm volatile("tcgen05.st.sync.aligned.32x32b.x32.b32 [%0], " \
        "{%1,%2,%3,%4,%5,%6,%7,%8,%9,%10,%11,%12,%13,%14,%15,%16," \
        "%17,%18,%19,%20,%21,%22,%23,%24,%25,%26,%27,%28,%29,%30,%31,%32};" \
        :: "r"(t), \
           "r"((r)[0]),"r"((r)[1]),"r"((r)[2]),"r"((r)[3]),"r"((r)[4]),"r"((r)[5]),"r"((r)[6]),"r"((r)[7]), \
           "r"((r)[8]),"r"((r)[9]),"r"((r)[10]),"r"((r)[11]),"r"((r)[12]),"r"((r)[13]),"r"((r)[14]),"r"((r)[15]), \
           "r"((r)[16]),"r"((r)[17]),"r"((r)[18]),"r"((r)[19]),"r"((r)[20]),"r"((r)[21]),"r"((r)[22]),"r"((r)[23]), \
           "r"((r)[24]),"r"((r)[25]),"r"((r)[26]),"r"((r)[27]),"r"((r)[28]),"r"((r)[29]),"r"((r)[30]),"r"((r)[31]) \
        : "memory")

#if TC_OK
// SW128 K-major smem descriptor: LBO=1 (16B), SBO=64 (1024B), version=1, SW128
__device__ __forceinline__ uint64_t make_desc(uint32_t addr) {
    const uint64_t base = (uint64_t(2) << 61) | (uint64_t(1) << 46)
                        | (uint64_t(64) << 32) | (uint64_t(1) << 16);
    return base | ((uint64_t)(addr >> 4) & 0x3FFF);
}
__device__ __forceinline__ void mma_tf32(uint32_t d, uint64_t ad, uint64_t bd,
                                         uint32_t idesc, bool acc) {
    uint32_t en = acc ? 1u : 0u;
    asm volatile(
        "{\n\t.reg .pred p;\n\tsetp.ne.u32 p, %5, 0;\n\t"
        "tcgen05.mma.cta_group::1.kind::tf32 [%0], %1, %2, %3, {%4,%4,%4,%4}, p;\n\t}"
        :: "r"(d), "l"(ad), "l"(bd), "r"(idesc), "r"(0u), "r"(en) : "memory");
}
__device__ __forceinline__ void mma_tf32_ts(uint32_t d, uint32_t a, uint64_t bd,
                                            uint32_t idesc, bool acc) {
    uint32_t en = acc ? 1u : 0u;
    asm volatile(
        "{\n\t.reg .pred p;\n\tsetp.ne.u32 p, %5, 0;\n\t"
        "tcgen05.mma.cta_group::1.kind::tf32 [%0], [%1], %2, %3, {%4,%4,%4,%4}, p;\n\t}"
        :: "r"(d), "r"(a), "l"(bd), "r"(idesc), "r"(0u), "r"(en) : "memory");
}
#endif

// ---------------- prep: LN1 + all 4 weight transposes in ONE launch -----------
// blocks [0, 8192): LN1 row.  blocks [8192, 12800): transpose tile (linear map).
__global__ __launch_bounds__(256)
void prep_kernel(const float* __restrict__ x, const float* __restrict__ g1,
                 const float* __restrict__ b1, float* __restrict__ hout,
                 const float* __restrict__ Wq, float* __restrict__ Tq,
                 const float* __restrict__ Wp, float* __restrict__ Tp,
                 const float* __restrict__ W1, float* __restrict__ T1,
                 const float* __restrict__ W2, float* __restrict__ T2)
{
    const int bid = blockIdx.x;
    const int tid = threadIdx.x;

    if (bid < MROWS) {
        // ---- LayerNorm row ----
        const float* xr = x + (size_t)bid * DIM;
        float v0 = xr[tid], v1 = xr[tid + 256], v2 = xr[tid + 512];
        float s  = v0 + v1 + v2;
        float ss = fmaf(v0, v0, fmaf(v1, v1, v2 * v2));
        #pragma unroll
        for (int o = 16; o > 0; o >>= 1) {
            s  += __shfl_xor_sync(0xffffffffu, s,  o);
            ss += __shfl_xor_sync(0xffffffffu, ss, o);
        }
        __shared__ float rs[8], rss[8];
        int w = tid >> 5, l = tid & 31;
        if (l == 0) { rs[w] = s; rss[w] = ss; }
        __syncthreads();
        float ts = 0.f, tss = 0.f;
        #pragma unroll
        for (int i = 0; i < 8; i++) { ts += rs[i]; tss += rss[i]; }
        const float inv_n = 1.0f / (float)DIM;
        float mu   = ts * inv_n;
        float var  = tss * inv_n - mu * mu;
        float rstd = rsqrtf(var + 1e-5f);
        float* orow = hout + (size_t)bid * DIM;
        orow[tid      ] = (v0 - mu) * rstd * g1[tid      ] + b1[tid      ];
        orow[tid + 256] = (v1 - mu) * rstd * g1[tid + 256] + b1[tid + 256];
        orow[tid + 512] = (v2 - mu) * rstd * g1[tid + 512] + b1[tid + 512];
    } else {
        // ---- transpose tile (no dead blocks) ----
        int id = bid - MROWS;
        const float* W; float* T; int K, N, bx, by;
        if (id < 1728)      { W = Wq; T = Tq; K = DIM;    N = 3*DIM;  bx = id % 72;        by = id / 72; }
        else if (id < 2304) { W = Wp; T = Tp; K = DIM;    N = DIM;    bx = (id-1728) % 24; by = (id-1728) / 24; }
        else if (id < 3456) { W = W1; T = T1; K = DIM;    N = HIDDEN; bx = (id-2304) % 48; by = (id-2304) / 48; }
        else                { W = W2; T = T2; K = HIDDEN; N = DIM;    bx = (id-3456) % 24; by = (id-3456) / 24; }

        __shared__ float t[32][33];
        int tx = tid & 31, ty = tid >> 5;
        #pragma unroll
        for (int i = 0; i < 4; i++)
            t[ty + i * 8][tx] = W[(size_t)(by * 32 + ty + i * 8) * N + bx * 32 + tx];
        __syncthreads();
        #pragma unroll
        for (int i = 0; i < 4; i++)
            T[(size_t)(bx * 32 + ty + i * 8) * K + by * 32 + tx] = t[tx][ty + i * 8];
    }
}

// ---------------- LayerNorm (LN2 only) ----------------------------------------
__global__ __launch_bounds__(256)
void ln_kernel(const float* __restrict__ x, const float* __restrict__ g,
               const float* __restrict__ b, float* __restrict__ out)
{
    int row = blockIdx.x;
    int tid = threadIdx.x;
    const float* xr = x + (size_t)row * DIM;

    float v0 = xr[tid], v1 = xr[tid + 256], v2 = xr[tid + 512];
    float s  = v0 + v1 + v2;
    float ss = fmaf(v0, v0, fmaf(v1, v1, v2 * v2));

    #pragma unroll
    for (int o = 16; o > 0; o >>= 1) {
        s  += __shfl_xor_sync(0xffffffffu, s,  o);
        ss += __shfl_xor_sync(0xffffffffu, ss, o);
    }
    __shared__ float rs[8], rss[8];
    int w = tid >> 5, l = tid & 31;
    if (l == 0) { rs[w] = s; rss[w] = ss; }
    __syncthreads();
    float ts = 0.f, tss = 0.f;
    #pragma unroll
    for (int i = 0; i < 8; i++) { ts += rs[i]; tss += rss[i]; }

    const float inv_n = 1.0f / (float)DIM;
    float mu   = ts * inv_n;
    float var  = tss * inv_n - mu * mu;
    float rstd = rsqrtf(var + 1e-5f);

    float* orow = out + (size_t)row * DIM;
    orow[tid      ] = (v0 - mu) * rstd * g[tid      ] + b[tid      ];
    orow[tid + 256] = (v1 - mu) * rstd * g[tid + 256] + b[tid + 256];
    orow[tid + 512] = (v2 - mu) * rstd * g[tid + 512] + b[tid + 512];
}

// ---------------- tcgen05 tf32 GEMM: 128x256 tile, 2-stage, 2 CTAs/SM ---------
#define EPI_QKV      0
#define EPI_BIASRES  1
#define EPI_BIASGELU 2

#define STG_BYTES 49152
#define TG_SMEM   (1024 + 2*STG_BYTES)    // 99328 -> 2 CTAs/SM

template<int EPI>
__global__ __launch_bounds__(256, 2)
void tgemm_kernel(const float* __restrict__ A, const float* __restrict__ Bt,
                  int M, int N, int K,
                  const float* __restrict__ bias, const float* __restrict__ res,
                  float* __restrict__ C,
                  float* __restrict__ Cq, float* __restrict__ Ck, float* __restrict__ Cv)
{
#if TC_OK
    extern __shared__ char sm[];
    const uint32_t smb = smem_u32(sm);
    const int tid = threadIdx.x;
    const int wid = tid >> 5;
    const int lid = tid & 31;
    const int m0 = blockIdx.y * 128;
    const int n0 = blockIdx.x * 256;
    const int nk = K / 32;

    const uint32_t OFF_TM = 0, MB = 8;
    const uint32_t OFF_S  = 1024;

    if (wid == 0) { TC_ALLOC(smb + OFF_TM, 256); TC_RELINQ(); }
    if (tid == 0) { MBAR_INIT(smb + MB, 1); MBAR_INIT(smb + MB + 8, 1); }
    __syncthreads();
    uint32_t tmem;
    asm volatile("ld.shared.b32 %0, [%1];" : "=r"(tmem) : "r"(smb + OFF_TM));
    TC_FENCE_AFTER();

    const uint32_t idesc = (1u << 4) | (2u << 7) | (2u << 10)
                         | (16u << 17) | (8u << 24);

    auto load_chunk = [&](int c, int st) {
        const int k0 = c * 32;
        const uint32_t base = smb + OFF_S + st * STG_BYTES;
        #pragma unroll
        for (int t = 0; t < 4; t++) {
            int id  = tid + t * 256;
            int row = id >> 3;
            int kc4 = (id & 7) * 4;
            uint32_t byte = row * 128 + kc4 * 4;
            uint32_t sw   = byte ^ ((byte >> 3) & 0x70);
            CP_ASYNC16(base + sw, A + (size_t)(m0 + row) * K + k0 + kc4);
        }
        #pragma unroll
        for (int t = 0; t < 8; t++) {
            int id  = tid + t * 256;
            int row = id >> 3;
            int kc4 = (id & 7) * 4;
            uint32_t byte = row * 128 + kc4 * 4;
            uint32_t sw   = byte ^ ((byte >> 3) & 0x70);
            CP_ASYNC16(base + 16384 + sw, Bt + (size_t)(n0 + row) * K + k0 + kc4);
        }
        CP_COMMIT();
    };

    load_chunk(0, 0); load_chunk(1, 1);

    for (int c = 0; c < nk; c++) {
        const int st = c & 1;
        CP_WAIT1();
        __syncthreads();
        FENCE_ASYNC();
        if (wid == 0) {
            const uint32_t base = smb + OFF_S + st * STG_BYTES;
            uint64_t ad  = make_desc(base);
            uint64_t bd0 = make_desc(base + 16384);
            uint64_t bd1 = make_desc(base + 32768);
            if (elect_one()) {
                #pragma unroll
                for (int ks = 0; ks < 4; ks++) {
                    bool acc = (c > 0) || (ks > 0);
                    mma_tf32(tmem,       ad + ks * 2, bd0 + ks * 2, idesc, acc);
                    mma_tf32(tmem + 128, ad + ks * 2, bd1 + ks * 2, idesc, acc);
                }
                TC_COMMIT(smb + MB + st * 8);
            }
        }
        if (c + 2 < nk) {
            MBAR_WAIT(smb + MB + st * 8, (c >> 1) & 1);
            load_chunk(c + 2, st);
        } else {
            CP_COMMIT();
        }
    }
    MBAR_WAIT(smb + MB + ((nk - 1) & 1) * 8, ((nk - 1) >> 1) & 1);
    TC_FENCE_AFTER();

    const int rw = wid & 3, ch = wid >> 2;
    const int r  = m0 + rw * 32 + lid;
    #pragma unroll
    for (int g = 0; g < 4; g++) {
        const int col0 = ch * 128 + g * 32;
        uint32_t d[32];
        TC_LD_X32(d, tmem + col0);
        TC_WAIT_LD();
        const int cbase = n0 + col0;
        if (EPI == EPI_QKV) {
            int which = cbase / DIM;
            int rem   = cbase - which * DIM;
            int h     = rem >> 6;
            int d0    = rem & 63;
            int bb    = r >> 10, n = r & 1023;
            if (which == 2) {
                float* dstv = Cv + ((size_t)(bb * HEADS + h) * HD + d0) * SEQ + n;
                #pragma unroll
                for (int j = 0; j < 32; j++)
                    dstv[(size_t)j * SEQ] = __uint_as_float(d[j]);
            } else {
                const float sc = (which == 0) ? 0.125f : 1.0f;
                float* p = (which == 0) ? Cq : Ck;
                float* dst = p + (((size_t)(bb * HEADS + h) * SEQ + n) * HD + d0);
                #pragma unroll
                for (int j4 = 0; j4 < 8; j4++)
                    *(float4*)(dst + j4 * 4) = make_float4(
                        __uint_as_float(d[j4*4+0]) * sc, __uint_as_float(d[j4*4+1]) * sc,
                        __uint_as_float(d[j4*4+2]) * sc, __uint_as_float(d[j4*4+3]) * sc);
            }
        } else if (EPI == EPI_BIASRES) {
            const float4* rp = (const float4*)(res  + (size_t)r * N + cbase);
            const float4* bp = (const float4*)(bias + cbase);
            float4*       cp = (float4*)(C + (size_t)r * N + cbase);
            #pragma unroll
            for (int j4 = 0; j4 < 8; j4++) {
                float4 rv = rp[j4], bv = bp[j4], o;
                o.x = rv.x + __uint_as_float(d[j4*4+0]) + bv.x;
                o.y = rv.y + __uint_as_float(d[j4*4+1]) + bv.y;
                o.z = rv.z + __uint_as_float(d[j4*4+2]) + bv.z;
                o.w = rv.w + __uint_as_float(d[j4*4+3]) + bv.w;
                cp[j4] = o;
            }
        } else {
            const float4* bp = (const float4*)(bias + cbase);
            float4*       cp = (float4*)(C + (size_t)r * N + cbase);
            #pragma unroll
            for (int j4 = 0; j4 < 8; j4++) {
                float4 bv = bp[j4], o;
                float t0 = __uint_as_float(d[j4*4+0]) + bv.x;
                float t1 = __uint_as_float(d[j4*4+1]) + bv.y;
                float t2 = __uint_as_float(d[j4*4+2]) + bv.z;
                float t3 = __uint_as_float(d[j4*4+3]) + bv.w;
                o.x = 0.5f * t0 * (1.0f + erff(t0 * 0.70710678118654752f));
                o.y = 0.5f * t1 * (1.0f + erff(t1 * 0.70710678118654752f));
                o.z = 0.5f * t2 * (1.0f + erff(t2 * 0.70710678118654752f));
                o.w = 0.5f * t3 * (1.0f + erff(t3 * 0.70710678118654752f));
                cp[j4] = o;
            }
        }
    }
    TC_FENCE_BEFORE();
    __syncthreads();
    if (wid == 0) {
        TC_DEALLOC(tmem, 256);
    }
#endif
}

// ---------------- tcgen05 flash attention v9 (proven, unchanged) --------------
#define NT 16
#define AT_SMEM (1024 + 32768 + 2*16384 + 3*16384)   // 115712 -> 2 CTAs/SM

__global__ __launch_bounds__(256, 2)
void attn_tc_kernel(const float* __restrict__ Q, const float* __restrict__ K,
                    const float* __restrict__ Vt, const float* __restrict__ rpe,
                    float* __restrict__ out)
{
#if TC_OK
    extern __shared__ char sm[];
    const uint32_t smb = smem_u32(sm);
    const int tid = threadIdx.x;
    const int wid = tid >> 5;
    const int lid = tid & 31;
    const int g   = wid >> 2;
    const int lw  = wid & 3;
    const int rsub = lw * 32 + lid;
    const int gtid = tid & 127;

    const int b  = blockIdx.x;
    const int hq = blockIdx.y;
    const int h  = hq >> 3;
    const int qt = hq & 7;
    const int bh = b * HEADS + h;
    const int q0 = qt * 128;

    const uint32_t OFF_TM = 0;
    const uint32_t MB1 = 8, MB2 = 24, FIN = 40;
    const uint32_t OFF_Q = 1024;
    const uint32_t OFF_K = 1024 + 32768;
    const uint32_t OFF_V = 1024 + 32768 + 32768;

    if (wid == 0) { TC_ALLOC(smb + OFF_TM, 256); TC_RELINQ(); }
    if (tid == 0) {
        MBAR_INIT(smb + MB1, 1); MBAR_INIT(smb + MB1 + 8, 1);
        MBAR_INIT(smb + MB2, 1); MBAR_INIT(smb + MB2 + 8, 1);
        MBAR_INIT(smb + FIN, 1); MBAR_INIT(smb + FIN + 8, 1);
    }
    __syncthreads();
    uint32_t tmem;
    asm volatile("ld.shared.b32 %0, [%1];" : "=r"(tmem) : "r"(smb + OFF_TM));
    TC_FENCE_AFTER();
    const uint32_t tmem_S = tmem + g * 64;
    const uint32_t tmem_O = tmem + 128;

    if (g == 0) {
        uint32_t z[32];
        #pragma unroll
        for (int i = 0; i < 32; i++) z[i] = 0u;
        TC_ST_X32(tmem_O, z);
        TC_ST_X32(tmem_O + 32, z);
        TC_WAIT_ST();
        TC_FENCE_BEFORE();
    }

    const float* Qb  = Q  + ((size_t)bh * SEQ + q0) * HD;
    const float* Kb0 = K  + (size_t)bh * SEQ * HD;
    const float* Vb0 = Vt + (size_t)bh * HD * SEQ;

    auto load_K_all = [&](int t2, int kslot) {
        const int kv0 = t2 * 64;
        #pragma unroll
        for (int t = 0; t < 4; t++) {
            int id  = tid + t * 256;
            int row = id >> 4;
            int c4  = (id & 15) * 4;
            int chunk = c4 >> 5;
            uint32_t byte = row * 128 + (c4 & 31) * 4;
            uint32_t sw   = byte ^ ((byte >> 3) & 0x70);
            CP_ASYNC16(smb + OFF_K + kslot * 16384 + chunk * 8192 + sw,
                       Kb0 + (size_t)(kv0 + row) * HD + c4);
        }
    };
    auto load_V_all = [&](int t2) {
        const int kv0 = t2 * 64, vslot = t2 % 3;
        #pragma unroll
        for (int t = 0; t < 4; t++) {
            int id  = tid + t * 256;
            int row = id >> 4;
            int c4  = (id & 15) * 4;
            int chunk = c4 >> 5;
            uint32_t byte = row * 128 + (c4 & 31) * 4;
            uint32_t sw   = byte ^ ((byte >> 3) & 0x70);
            CP_ASYNC16(smb + OFF_V + vslot * 16384 + chunk * 8192 + sw,
                       Vb0 + (size_t)row * SEQ + kv0 + c4);
        }
    };
    auto load_K_grp = [&](int t2) {
        const int kv0 = t2 * 64;
        #pragma unroll
        for (int t = 0; t < 8; t++) {
            int id  = gtid + t * 128;
            int row = id >> 4;
            int c4  = (id & 15) * 4;
            int chunk = c4 >> 5;
            uint32_t byte = row * 128 + (c4 & 31) * 4;
            uint32_t sw   = byte ^ ((byte >> 3) & 0x70);
            CP_ASYNC16(smb + OFF_K + g * 16384 + chunk * 8192 + sw,
                       Kb0 + (size_t)(kv0 + row) * HD + c4);
        }
    };
    auto load_V_grp = [&](int t2) {
        const int kv0 = t2 * 64, vslot = t2 % 3;
        #pragma unroll
        for (int t = 0; t < 8; t++) {
            int id  = gtid + t * 128;
            int row = id >> 4;
            int c4  = (id & 15) * 4;
            int chunk = c4 >> 5;
            uint32_t byte = row * 128 + (c4 & 31) * 4;
            uint32_t sw   = byte ^ ((byte >> 3) & 0x70);
            CP_ASYNC16(smb + OFF_V + vslot * 16384 + chunk * 8192 + sw,
                       Vb0 + (size_t)row * SEQ + kv0 + c4);
        }
    };

    // prologue
    #pragma unroll
    for (int t = 0; t < 8; t++) {
        int id  = tid + t * 256;
        int row = id >> 4;
        int c4  = (id & 15) * 4;
        int chunk = c4 >> 5;
        uint32_t byte = row * 128 + (c4 & 31) * 4;
        uint32_t sw   = byte ^ ((byte >> 3) & 0x70);
        CP_ASYNC16(smb + OFF_Q + chunk * 16384 + sw, Qb + row * HD + c4);
    }
    load_K_all(0, 0); load_V_all(0);
    load_K_all(1, 1); load_V_all(1);
    CP_COMMIT();
    CP_WAIT0();
    __syncthreads();
    FENCE_ASYNC();

    const uint32_t idesc1 = (1u << 4) | (2u << 7) | (2u << 10)
                          | (8u << 17) | (8u << 24);

    float lsum = 0.f;

    for (int j = 0; j < 8; j++) {
        const int t = 2 * j + g;

        CP_WAIT0();
        BAR_SYNC_N(1 + g);
        FENCE_ASYNC();

        if (lw == 0) {
            TC_FENCE_AFTER();
            if (elect_one()) {
                #pragma unroll
                for (int c = 0; c < 2; c++) {
                    uint64_t ad = make_desc(smb + OFF_Q + c * 16384);
                    uint64_t bd = make_desc(smb + OFF_K + g * 16384 + c * 8192);
                    #pragma unroll
                    for (int ks = 0; ks < 4; ks++)
                        mma_tf32(tmem_S, ad + ks * 2, bd + ks * 2, idesc1,
                                 (c > 0) || (ks > 0));
                }
                TC_COMMIT(smb + MB1 + g * 8);
            }
        }

        const float4* bp = (const float4*)(rpe + ((size_t)h * SEQ + q0 + rsub) * SEQ
                                           + t * 64);
        float4 b0[8];
        #pragma unroll
        for (int i = 0; i < 8; i++) b0[i] = bp[i];

        if (j < 7) {
            const int gate = j + g - 1;
            if (gate >= 0) MBAR_WAIT(smb + MB2 + (1 - g) * 8, gate & 1);
            load_V_grp(t + 2);
            CP_COMMIT();
        }

        MBAR_WAIT(smb + MB1 + g * 8, j & 1);
        TC_FENCE_AFTER();

        if (j < 7) { load_K_grp(t + 2); CP_COMMIT(); }

        {
            uint32_t d[32];
            TC_LD_X32(d, tmem_S);
            TC_WAIT_LD();
            float4 b1[8];
            #pragma unroll
            for (int i = 0; i < 8; i++) b1[i] = bp[8 + i];
            #pragma unroll
            for (int j4 = 0; j4 < 8; j4++) {
                float4 bv = b0[j4];
                float p0 = __expf(__uint_as_float(d[j4*4+0]) + bv.x);
                float p1 = __expf(__uint_as_float(d[j4*4+1]) + bv.y);
                float p2 = __expf(__uint_as_float(d[j4*4+2]) + bv.z);
                float p3 = __expf(__uint_as_float(d[j4*4+3]) + bv.w);
                lsum += (p0 + p1) + (p2 + p3);
                d[j4*4+0] = __float_as_uint(p0);
                d[j4*4+1] = __float_as_uint(p1);
                d[j4*4+2] = __float_as_uint(p2);
                d[j4*4+3] = __float_as_uint(p3);
            }
            TC_ST_X32(tmem_S, d);
            TC_LD_X32(d, tmem_S + 32);
            TC_WAIT_LD();
            #pragma unroll
            for (int j4 = 0; j4 < 8; j4++) {
                float4 bv = b1[j4];
                float p0 = __expf(__uint_as_float(d[j4*4+0]) + bv.x);
                float p1 = __expf(__uint_as_float(d[j4*4+1]) + bv.y);
                float p2 = __expf(__uint_as_float(d[j4*4+2]) + bv.z);
                float p3 = __expf(__uint_as_float(d[j4*4+3]) + bv.w);
                lsum += (p0 + p1) + (p2 + p3);
                d[j4*4+0] = __float_as_uint(p0);
                d[j4*4+1] = __float_as_uint(p1);
                d[j4*4+2] = __float_as_uint(p2);
                d[j4*4+3] = __float_as_uint(p3);
            }
            TC_ST_X32(tmem_S + 32, d);
            TC_WAIT_ST();
            TC_FENCE_BEFORE();
        }

        if (lw == 0) {
            BAR_SYNC_N(3 + g);
            TC_FENCE_AFTER();
            if (elect_one()) {
                const int vs = t % 3;
                #pragma unroll
                for (int s = 0; s < 8; s++) {
                    uint64_t bd = make_desc(smb + OFF_V + vs * 16384 + (s >> 2) * 8192)
                                + (s & 3) * 2;
                    mma_tf32_ts(tmem_O, tmem_S + s * 8, bd, idesc1, true);
                }
                TC_COMMIT(smb + MB2 + g * 8);
                if (j == 7) TC_COMMIT(smb + FIN + g * 8);
            }
        } else {
            BAR_ARRIVE_N(3 + g);
        }
    }

    __syncthreads();
    MBAR_WAIT(smb + FIN, 0);
    MBAR_WAIT(smb + FIN + 8, 0);
    TC_FENCE_AFTER();

    float* lsh = (float*)(sm + OFF_V);
    lsh[g * 128 + rsub] = lsum;
    __syncthreads();
    const float inv = 1.0f / (lsh[rsub] + lsh[128 + rsub]);

    {
        uint32_t d[32];
        TC_LD_X32(d, tmem_O + g * 32);
        TC_WAIT_LD();
        float* ob = out + ((size_t)(b * SEQ + q0 + rsub)) * DIM + h * HD + g * 32;
        #pragma unroll
        for (int j4 = 0; j4 < 8; j4++)
            *(float4*)(ob + j4 * 4) = make_float4(
                __uint_as_float(d[j4*4+0]) * inv, __uint_as_float(d[j4*4+1]) * inv,
                __uint_as_float(d[j4*4+2]) * inv, __uint_as_float(d[j4*4+3]) * inv);
    }
    TC_FENCE_BEFORE();
    __syncthreads();
    if (wid == 0) {
        TC_DEALLOC(tmem, 256);
    }
#endif
}

// ---------------- launch: 7 kernels -------------------------------------------
extern "C" void kernel_launch(void* const* d_in, const int* in_sizes, int n_in,
                              void* d_out, int out_size)
{
    const float* x      = (const float*)d_in[0];
    const float* rpe    = (const float*)d_in[1];
    const float* qkv_w  = (const float*)d_in[2];
    const float* proj_w = (const float*)d_in[3];
    const float* proj_b = (const float*)d_in[4];
    const float* ln1_g  = (const float*)d_in[5];
    const float* ln1_b  = (const float*)d_in[6];
    const float* ln2_g  = (const float*)d_in[7];
    const float* ln2_b  = (const float*)d_in[8];
    const float* fc1_w  = (const float*)d_in[9];
    const float* fc1_b  = (const float*)d_in[10];
    const float* fc2_w  = (const float*)d_in[11];
    const float* fc2_b  = (const float*)d_in[12];
    float* out = (float*)d_out;

    float *p_h, *p_q, *p_k, *p_v, *p_attn, *p_x1, *p_hid;
    float *p_wq, *p_wp, *p_w1, *p_w2;
    cudaGetSymbolAddress((void**)&p_h,    g_h);
    cudaGetSymbolAddress((void**)&p_q,    g_q);
    cudaGetSymbolAddress((void**)&p_k,    g_k);
    cudaGetSymbolAddress((void**)&p_v,    g_v);
    cudaGetSymbolAddress((void**)&p_attn, g_attn);
    cudaGetSymbolAddress((void**)&p_x1,   g_x1);
    cudaGetSymbolAddress((void**)&p_hid,  g_hid);
    cudaGetSymbolAddress((void**)&p_wq,   g_wT_qkv);
    cudaGetSymbolAddress((void**)&p_wp,   g_wT_proj);
    cudaGetSymbolAddress((void**)&p_w1,   g_wT_fc1);
    cudaGetSymbolAddress((void**)&p_w2,   g_wT_fc2);

    cudaFuncSetAttribute(attn_tc_kernel,
                         cudaFuncAttributeMaxDynamicSharedMemorySize, AT_SMEM);
    cudaFuncSetAttribute(tgemm_kernel<EPI_QKV>,
                         cudaFuncAttributeMaxDynamicSharedMemorySize, TG_SMEM);
    cudaFuncSetAttribute(tgemm_kernel<EPI_BIASRES>,
                         cudaFuncAttributeMaxDynamicSharedMemorySize, TG_SMEM);
    cudaFuncSetAttribute(tgemm_kernel<EPI_BIASGELU>,
                         cudaFuncAttributeMaxDynamicSharedMemorySize, TG_SMEM);

    // 1) prep: LN1 + all 4 weight transposes, one launch
    prep_kernel<<<MROWS + 4608, 256>>>(
        x, ln1_g, ln1_b, p_h,
        qkv_w, p_wq, proj_w, p_wp, fc1_w, p_w1, fc2_w, p_w2);

    // 2) QKV GEMM (Q pre-scaled, V scattered transposed)
    tgemm_kernel<EPI_QKV><<<dim3(3 * DIM / 256, MROWS / 128), 256, TG_SMEM>>>(
        p_h, p_wq, MROWS, 3 * DIM, DIM,
        nullptr, nullptr, nullptr, p_q, p_k, p_v);

    // 3) two-warp-group tensor-core flash attention (v9)
    attn_tc_kernel<<<dim3(BATCH, HEADS * (SEQ / 128)), 256, AT_SMEM>>>(
        p_q, p_k, p_v, rpe, p_attn);

    // 4) proj + bias + residual
    tgemm_kernel<EPI_BIASRES><<<dim3(DIM / 256, MROWS / 128), 256, TG_SMEM>>>(
        p_attn, p_wp, MROWS, DIM, DIM,
        proj_b, x, p_x1, nullptr, nullptr, nullptr);

    // 5) LN2
    ln_kernel<<<MROWS, 256>>>(p_x1, ln2_g, ln2_b, p_h);

    // 6) FC1 + GELU
    tgemm_kernel<EPI_BIASGELU><<<dim3(HIDDEN / 256, MROWS / 128), 256, TG_SMEM>>>(
        p_h, p_w1, MROWS, HIDDEN, DIM,
        fc1_b, nullptr, p_hid, nullptr, nullptr, nullptr);

    // 7) FC2 + bias + residual
    tgemm_kernel<EPI_BIASRES><<<dim3(DIM / 256, MROWS / 128), 256, TG_SMEM>>>(
        p_hid, p_w2, MROWS, DIM, HIDDEN,
        fc2_b, p_x1, out, nullptr, nullptr, nullptr);
}